// round 10
// baseline (speedup 1.0000x reference)
#include <cuda_runtime.h>

// FeatureFuser: out = sigmoid( last-write-wins(sampling_map, refined[k] over window_k) )
// B=8, TOP_K=4, C=32, H=W=256, GRID=4 (cell 64x64), WINDOW=3 cells (192x192, clipped).
//
// Per output pixel exactly one source is read: refined[b, k_win, c, h, w] where
// k_win = max k whose window contains (h,w), else sampling_map[b,c,h,w].
//
// R10: loads stay on the R8 register path (LDG.128, MLP=4, 28 regs, warp-
// coalesced 512B). Stores move OFF the LSU: sigmoid results staged in SMEM,
// then one elected thread issues a single cp.async.bulk (TMA, UTMASTG/UBLKCP)
// pushing the block's contiguous 16 KB output slice. This removes all 131K
// STG.128 warp-instructions from the LSU/L1tex path and converts the 67 MB
// write stream into 16 KB contiguous bursts (better DRAM write drain), testing
// the hypothesis that the store pipe is the unmeasured ~19.4us cap.
//
// w4 = tid & 63 invariant per thread -> x-predicates and base pointers hoisted.
// regions arrive as int32 (JAX x64 disabled downcasts the int64 request).

#define B_      8
#define K_      4
#define C_      32
#define H_      256
#define W_      256
#define W4_     (W_/4)
#define PLANE4  (H_*W_/4)      // 16384 float4s per (b,c) plane
#define V_      4              // float4s per thread, warp-strided

__device__ __forceinline__ float fast_sigmoid(float x) {
    float t;
    asm("tanh.approx.f32 %0, %1;" : "=f"(t) : "f"(0.5f * x));
    return fmaf(0.5f, t, 0.5f);
}

__global__ void __launch_bounds__(256, 8)
feature_fuser_kernel(const float* __restrict__ smap,
                     const float* __restrict__ rmap,
                     const int* __restrict__ regions,
                     float* __restrict__ out)
{
    __shared__ float4 stage[V_ * 256];               // 16 KB output staging

    const int tid = threadIdx.x;
    const int w4  = tid & (W4_ - 1);                 // invariant per thread
    const int blockBase = blockIdx.x * (256 * V_);   // float4 index
    const int bc = blockBase >> 14;                  // uniform per block
    const int c  = bc & (C_ - 1);
    const int b  = bc >> 5;
    const int hbase = ((blockBase >> 6) & (H_ - 1)) + (tid >> 6);

    // Hoisted per-k state: y-range and x-predicate (x fixed per thread).
    int ys[K_]; unsigned ylen[K_]; bool xok[K_];
    #pragma unroll
    for (int k = 0; k < K_; ++k) {
        ys[k]   = __ldg(&regions[(b * K_ + k) * 2 + 0]) << 6;
        int xs4 =  __ldg(&regions[(b * K_ + k) * 2 + 1]) << 4;   // float4 units
        ylen[k] = (unsigned)(min(ys[k] + 192, H_) - ys[k]);
        xok[k]  = (unsigned)(w4 - xs4) < (unsigned)(min(xs4 + 48, W4_) - xs4);
    }

    // Per-k source base pointers with w4 folded in.
    const float4* s4 = reinterpret_cast<const float4*>(smap) + (size_t)bc * PLANE4 + w4;
    const float4* r4 = reinterpret_cast<const float4*>(rmap)
                     + ((size_t)(b * K_) * C_ + c) * PLANE4 + w4;

    float4 v[V_];
    #pragma unroll
    for (int i = 0; i < V_; ++i) {
        int h = hbase + 4 * i;
        const float4* p = s4;
        #pragma unroll
        for (int k = 0; k < K_; ++k) {               // ascending: last write wins
            bool inside = xok[k] & ((unsigned)(h - ys[k]) < ylen[k]);
            const float4* pk = r4 + (size_t)k * (C_ * PLANE4);
            p = inside ? pk : p;
        }
        v[i] = __ldg(p + h * W4_);                   // MLP=4, front-batched
    }

    #pragma unroll
    for (int i = 0; i < V_; ++i) {
        v[i].x = fast_sigmoid(v[i].x);
        v[i].y = fast_sigmoid(v[i].y);
        v[i].z = fast_sigmoid(v[i].z);
        v[i].w = fast_sigmoid(v[i].w);
        stage[i * 256 + tid] = v[i];                 // STS.128, conflict-free
    }

    // Make generic-proxy SMEM writes visible to the async proxy, then one
    // elected thread pushes the whole contiguous 16 KB block via TMA bulk.
    __syncthreads();
    asm volatile("fence.proxy.async.shared::cta;" ::: "memory");
    if (tid == 0) {
        unsigned s = (unsigned)__cvta_generic_to_shared(stage);
        const float4* dst = reinterpret_cast<const float4*>(out) + blockBase;
        asm volatile(
            "cp.async.bulk.global.shared::cta.bulk_group [%0], [%1], %2;\n\t"
            "cp.async.bulk.commit_group;\n\t"
            "cp.async.bulk.wait_group.read 0;\n\t"
            :: "l"(dst), "r"(s), "r"(V_ * 256 * 16) : "memory");
    }
    // Other threads exit; block (and its SMEM) stays alive until tid 0's wait
    // completes, so the TMA read of `stage` is safe.
}

extern "C" void kernel_launch(void* const* d_in, const int* in_sizes, int n_in,
                              void* d_out, int out_size)
{
    const float* smap    = (const float*)d_in[0];
    const float* rmap    = (const float*)d_in[1];
    const int*   regions = (const int*)d_in[2];
    float*       out     = (float*)d_out;

    const int total4  = B_ * C_ * H_ * W_ / 4;       // 4,194,304 float4s
    const int threads = 256;
    const int blocks  = total4 / (threads * V_);     // 4096
    feature_fuser_kernel<<<blocks, threads>>>(smap, rmap, regions, out);
}

// round 11
// speedup vs baseline: 1.0992x; 1.0992x over previous
#include <cuda_runtime.h>

// FeatureFuser: out = sigmoid( last-write-wins(sampling_map, refined[k] over window_k) )
// B=8, TOP_K=4, C=32, H=W=256, GRID=4 (cell 64x64), WINDOW=3 cells (192x192, clipped).
//
// Per output pixel exactly one source is read: refined[b, k_win, c, h, w] where
// k_win = max k whose window contains (h,w), else sampling_map[b,c,h,w].
//
// R11 = R10 (register-path LDG.128 loads, SMEM-staged TMA bulk store) + an
// L2::evict_first cache-policy on the bulk store. R10 vs R8/R9 showed the
// split: TMA store wins cold (ncu 18.98us, no STG issue), but plain TMA
// writes allocate 67MB into L2 each replay and evict the source tensors,
// losing the steady-state residency that st.global.cs preserved (bench 23.0
// vs 20.6). createpolicy.fractional.L2::evict_first restores that behavior
// on the TMA path.
//
// w4 = tid & 63 invariant per thread -> x-predicates and base pointers hoisted.
// regions arrive as int32 (JAX x64 disabled downcasts the int64 request).

#define B_      8
#define K_      4
#define C_      32
#define H_      256
#define W_      256
#define W4_     (W_/4)
#define PLANE4  (H_*W_/4)      // 16384 float4s per (b,c) plane
#define V_      4              // float4s per thread, warp-strided

__device__ __forceinline__ float fast_sigmoid(float x) {
    float t;
    asm("tanh.approx.f32 %0, %1;" : "=f"(t) : "f"(0.5f * x));
    return fmaf(0.5f, t, 0.5f);
}

__global__ void __launch_bounds__(256, 8)
feature_fuser_kernel(const float* __restrict__ smap,
                     const float* __restrict__ rmap,
                     const int* __restrict__ regions,
                     float* __restrict__ out)
{
    __shared__ float4 stage[V_ * 256];               // 16 KB output staging

    const int tid = threadIdx.x;
    const int w4  = tid & (W4_ - 1);                 // invariant per thread
    const int blockBase = blockIdx.x * (256 * V_);   // float4 index
    const int bc = blockBase >> 14;                  // uniform per block
    const int c  = bc & (C_ - 1);
    const int b  = bc >> 5;
    const int hbase = ((blockBase >> 6) & (H_ - 1)) + (tid >> 6);

    // Hoisted per-k state: y-range and x-predicate (x fixed per thread).
    int ys[K_]; unsigned ylen[K_]; bool xok[K_];
    #pragma unroll
    for (int k = 0; k < K_; ++k) {
        ys[k]   = __ldg(&regions[(b * K_ + k) * 2 + 0]) << 6;
        int xs4 =  __ldg(&regions[(b * K_ + k) * 2 + 1]) << 4;   // float4 units
        ylen[k] = (unsigned)(min(ys[k] + 192, H_) - ys[k]);
        xok[k]  = (unsigned)(w4 - xs4) < (unsigned)(min(xs4 + 48, W4_) - xs4);
    }

    // Per-k source base pointers with w4 folded in.
    const float4* s4 = reinterpret_cast<const float4*>(smap) + (size_t)bc * PLANE4 + w4;
    const float4* r4 = reinterpret_cast<const float4*>(rmap)
                     + ((size_t)(b * K_) * C_ + c) * PLANE4 + w4;

    float4 v[V_];
    #pragma unroll
    for (int i = 0; i < V_; ++i) {
        int h = hbase + 4 * i;
        const float4* p = s4;
        #pragma unroll
        for (int k = 0; k < K_; ++k) {               // ascending: last write wins
            bool inside = xok[k] & ((unsigned)(h - ys[k]) < ylen[k]);
            const float4* pk = r4 + (size_t)k * (C_ * PLANE4);
            p = inside ? pk : p;
        }
        v[i] = __ldg(p + h * W4_);                   // MLP=4, front-batched
    }

    #pragma unroll
    for (int i = 0; i < V_; ++i) {
        v[i].x = fast_sigmoid(v[i].x);
        v[i].y = fast_sigmoid(v[i].y);
        v[i].z = fast_sigmoid(v[i].z);
        v[i].w = fast_sigmoid(v[i].w);
        stage[i * 256 + tid] = v[i];                 // STS.128, conflict-free
    }

    // Make generic-proxy SMEM writes visible to the async proxy, then one
    // elected thread pushes the contiguous 16 KB block via TMA bulk with an
    // evict-first L2 policy (output is never re-read; keep sources resident).
    __syncthreads();
    asm volatile("fence.proxy.async.shared::cta;" ::: "memory");
    if (tid == 0) {
        unsigned s = (unsigned)__cvta_generic_to_shared(stage);
        const float4* dst = reinterpret_cast<const float4*>(out) + blockBase;
        asm volatile(
            "{\n\t"
            ".reg .b64 pol;\n\t"
            "createpolicy.fractional.L2::evict_first.b64 pol, 1.0;\n\t"
            "cp.async.bulk.global.shared::cta.bulk_group.L2::cache_hint [%0], [%1], %2, pol;\n\t"
            "cp.async.bulk.commit_group;\n\t"
            "cp.async.bulk.wait_group.read 0;\n\t"
            "}"
            :: "l"(dst), "r"(s), "r"(V_ * 256 * 16) : "memory");
    }
    // Other threads exit; the block (and its SMEM) stays alive until tid 0's
    // wait completes, so the TMA read of `stage` is safe.
}

extern "C" void kernel_launch(void* const* d_in, const int* in_sizes, int n_in,
                              void* d_out, int out_size)
{
    const float* smap    = (const float*)d_in[0];
    const float* rmap    = (const float*)d_in[1];
    const int*   regions = (const int*)d_in[2];
    float*       out     = (float*)d_out;

    const int total4  = B_ * C_ * H_ * W_ / 4;       // 4,194,304 float4s
    const int threads = 256;
    const int blocks  = total4 / (threads * V_);     // 4096
    feature_fuser_kernel<<<blocks, threads>>>(smap, rmap, regions, out);
}

// round 12
// speedup vs baseline: 1.1410x; 1.0380x over previous
#include <cuda_runtime.h>

// FeatureFuser: out = sigmoid( last-write-wins(sampling_map, refined[k] over window_k) )
// B=8, TOP_K=4, C=32, H=W=256, GRID=4 (cell 64x64), WINDOW=3 cells (192x192, clipped).
//
// Per output pixel exactly one source is read: refined[b, k_win, c, h, w] where
// k_win = max k whose window contains (h,w), else sampling_map[b,c,h,w].
//
// R12 = R11 + L2::evict_last policy on the source loads.
// Traffic model: the per-replay read footprint is exactly 67 MB (one source
// value per output pixel, deterministic across graph replays) and fits in the
// 126 MB L2. Writes (67 MB) already bypass-ish via TMA bulk + evict_first.
// Marking reads evict_last pins the read set so steady-state replays read
// ~everything from L2 and HBM carries only the write stream.
//
// w4 = tid & 63 invariant per thread -> x-predicates and base pointers hoisted.
// regions arrive as int32 (JAX x64 disabled downcasts the int64 request).

#define B_      8
#define K_      4
#define C_      32
#define H_      256
#define W_      256
#define W4_     (W_/4)
#define PLANE4  (H_*W_/4)      // 16384 float4s per (b,c) plane
#define V_      4              // float4s per thread, warp-strided

__device__ __forceinline__ float fast_sigmoid(float x) {
    float t;
    asm("tanh.approx.f32 %0, %1;" : "=f"(t) : "f"(0.5f * x));
    return fmaf(0.5f, t, 0.5f);
}

__device__ __forceinline__ float4 ldg_evict_last(const float4* p, unsigned long long pol) {
    float4 v;
    asm volatile("ld.global.nc.L2::cache_hint.v4.f32 {%0,%1,%2,%3}, [%4], %5;"
                 : "=f"(v.x), "=f"(v.y), "=f"(v.z), "=f"(v.w)
                 : "l"(p), "l"(pol));
    return v;
}

__global__ void __launch_bounds__(256, 8)
feature_fuser_kernel(const float* __restrict__ smap,
                     const float* __restrict__ rmap,
                     const int* __restrict__ regions,
                     float* __restrict__ out)
{
    __shared__ float4 stage[V_ * 256];               // 16 KB output staging

    const int tid = threadIdx.x;
    const int w4  = tid & (W4_ - 1);                 // invariant per thread
    const int blockBase = blockIdx.x * (256 * V_);   // float4 index
    const int bc = blockBase >> 14;                  // uniform per block
    const int c  = bc & (C_ - 1);
    const int b  = bc >> 5;
    const int hbase = ((blockBase >> 6) & (H_ - 1)) + (tid >> 6);

    // Sticky-read policy: the 67 MB read set repeats every replay.
    unsigned long long pol_last;
    asm volatile("createpolicy.fractional.L2::evict_last.b64 %0, 1.0;" : "=l"(pol_last));

    // Hoisted per-k state: y-range and x-predicate (x fixed per thread).
    int ys[K_]; unsigned ylen[K_]; bool xok[K_];
    #pragma unroll
    for (int k = 0; k < K_; ++k) {
        ys[k]   = __ldg(&regions[(b * K_ + k) * 2 + 0]) << 6;
        int xs4 =  __ldg(&regions[(b * K_ + k) * 2 + 1]) << 4;   // float4 units
        ylen[k] = (unsigned)(min(ys[k] + 192, H_) - ys[k]);
        xok[k]  = (unsigned)(w4 - xs4) < (unsigned)(min(xs4 + 48, W4_) - xs4);
    }

    // Per-k source base pointers with w4 folded in.
    const float4* s4 = reinterpret_cast<const float4*>(smap) + (size_t)bc * PLANE4 + w4;
    const float4* r4 = reinterpret_cast<const float4*>(rmap)
                     + ((size_t)(b * K_) * C_ + c) * PLANE4 + w4;

    float4 v[V_];
    #pragma unroll
    for (int i = 0; i < V_; ++i) {
        int h = hbase + 4 * i;
        const float4* p = s4;
        #pragma unroll
        for (int k = 0; k < K_; ++k) {               // ascending: last write wins
            bool inside = xok[k] & ((unsigned)(h - ys[k]) < ylen[k]);
            const float4* pk = r4 + (size_t)k * (C_ * PLANE4);
            p = inside ? pk : p;
        }
        v[i] = ldg_evict_last(p + h * W4_, pol_last);   // MLP=4, front-batched
    }

    #pragma unroll
    for (int i = 0; i < V_; ++i) {
        v[i].x = fast_sigmoid(v[i].x);
        v[i].y = fast_sigmoid(v[i].y);
        v[i].z = fast_sigmoid(v[i].z);
        v[i].w = fast_sigmoid(v[i].w);
        stage[i * 256 + tid] = v[i];                 // STS.128, conflict-free
    }

    // Make generic-proxy SMEM writes visible to the async proxy, then one
    // elected thread pushes the contiguous 16 KB block via TMA bulk with an
    // evict-first L2 policy (output is never re-read; keep sources resident).
    __syncthreads();
    asm volatile("fence.proxy.async.shared::cta;" ::: "memory");
    if (tid == 0) {
        unsigned s = (unsigned)__cvta_generic_to_shared(stage);
        const float4* dst = reinterpret_cast<const float4*>(out) + blockBase;
        asm volatile(
            "{\n\t"
            ".reg .b64 pol;\n\t"
            "createpolicy.fractional.L2::evict_first.b64 pol, 1.0;\n\t"
            "cp.async.bulk.global.shared::cta.bulk_group.L2::cache_hint [%0], [%1], %2, pol;\n\t"
            "cp.async.bulk.commit_group;\n\t"
            "cp.async.bulk.wait_group.read 0;\n\t"
            "}"
            :: "l"(dst), "r"(s), "r"(V_ * 256 * 16) : "memory");
    }
    // Other threads exit; the block (and its SMEM) stays alive until tid 0's
    // wait completes, so the TMA read of `stage` is safe.
}

extern "C" void kernel_launch(void* const* d_in, const int* in_sizes, int n_in,
                              void* d_out, int out_size)
{
    const float* smap    = (const float*)d_in[0];
    const float* rmap    = (const float*)d_in[1];
    const int*   regions = (const int*)d_in[2];
    float*       out     = (float*)d_out;

    const int total4  = B_ * C_ * H_ * W_ / 4;       // 4,194,304 float4s
    const int threads = 256;
    const int blocks  = total4 / (threads * V_);     // 4096
    feature_fuser_kernel<<<blocks, threads>>>(smap, rmap, regions, out);
}